// round 12
// baseline (speedup 1.0000x reference)
#include <cuda_runtime.h>
#include <math.h>

#define Dn 384
#define Nn 96
#define TPB 256
#define FULLMASK 0xffffffffu

// Per-site chain vectors w_j = C_{j-1} v_j (current epoch), L2-resident.
__device__ float whist_g[Dn][Nn];

// Dynamic shared memory (~152 KB).
struct Smem {
    float P[Dn * Nn];                 // eigfunc[:, :96] row-major [site][comp]
    float qarr[Dn];                   // per-site pivot complement q (cur epoch)
    float probs[Dn];                  // window probs (current step)
    float cdfa[Dn];                   // running cdf (current step)
    __align__(16) float w[2][2 * Nn]; // heavy: [buf][ w1(96) | w2(96) ]
    __align__(16) float qpb[2][96];   // heavy: [buf][ q1p | sp | q2p ] x32
    __align__(16) float gfin[Nn];     // light: final correction vector
    float delta_s, run_s, cdf_s;
    int   jend_s, exited_s;
    int   cnt[8];
};

__device__ __forceinline__ float grcp(float x) {
    return (fabsf(x) > 1e-30f) ? __frcp_rn(x) : 0.0f;
}

__device__ __forceinline__ void load12(const float* src, float d[12]) {
    const float4* s4 = reinterpret_cast<const float4*>(src);
    float4 a = s4[0], b = s4[1], c = s4[2];
    d[0]=a.x; d[1]=a.y; d[2]=a.z; d[3]=a.w;
    d[4]=b.x; d[5]=b.y; d[6]=b.z; d[7]=b.w;
    d[8]=c.x; d[9]=c.y; d[10]=c.z; d[11]=c.w;
}

// Deterministic fixed-order sum of 32 floats (16B-aligned smem).
__device__ __forceinline__ float sum32(const float* q) {
    const float4* q4 = reinterpret_cast<const float4*>(q);
    float t[8];
#pragma unroll
    for (int i = 0; i < 8; i++) {
        float4 v = q4[i];
        t[i] = (v.x + v.y) + (v.z + v.w);
    }
    return ((t[0]+t[1]) + (t[2]+t[3])) + ((t[4]+t[5]) + (t[6]+t[7]));
}

// Balanced 12-term dot (4 accumulators), fixed order.
__device__ __forceinline__ float dot12(const float* c, const float v[12]) {
    float a = c[0]*v[0]; a = fmaf(c[4], v[4], a); a = fmaf(c[8],  v[8],  a);
    float b = c[1]*v[1]; b = fmaf(c[5], v[5], b); b = fmaf(c[9],  v[9],  b);
    float d = c[2]*v[2]; d = fmaf(c[6], v[6], d); d = fmaf(c[10], v[10], d);
    float e = c[3]*v[3]; e = fmaf(c[7], v[7], e); e = fmaf(c[11], v[11], e);
    return (a + b) + (d + e);
}

__device__ __forceinline__ void bfly5x3(float& a, float& b, float& c) {
#pragma unroll
    for (int off = 16; off; off >>= 1) {
        a += __shfl_xor_sync(FULLMASK, a, off);
        b += __shfl_xor_sync(FULLMASK, b, off);
        c += __shfl_xor_sync(FULLMASK, c, off);
    }
}
__device__ __forceinline__ float bfly5(float a) {
#pragma unroll
    for (int off = 16; off; off >>= 1)
        a += __shfl_xor_sync(FULLMASK, a, off);
    return a;
}

// ---------------------------------------------------------------------------
// Light pass (warp 0 only; lane l owns components 3l..3l+2).
// Epoch change = exactly rank-1: D = delta * g g^T, seeded by flipping site
// `pos` from empty-conditioned to occupied on the same prefix chain:
//   delta0 = -(1/q_pos + 1/(1-q_pos)),  g0 = w_pos  (stored, current epoch).
// Per-pair recursion IDENTICAL to the R10-passing version (division-free in
// computed dots; old-pivot reciprocals hoisted to prefetch time — same inputs,
// bitwise-same values). Triple-buffered depth-2 pair prefetch hides L2.
// ---------------------------------------------------------------------------

// prefetch pair (j+4, j+5) into buffer (WN, QN, IPN); guarded.
#define LP_PREF(WN, QN, IPN) do {                                            \
    if (j + 5 < F) {                                                         \
        WN[0][0] = whist_g[j+4][b0+0];                                       \
        WN[0][1] = whist_g[j+4][b0+1];                                       \
        WN[0][2] = whist_g[j+4][b0+2];                                       \
        WN[1][0] = whist_g[j+5][b0+0];                                       \
        WN[1][1] = whist_g[j+5][b0+1];                                       \
        WN[1][2] = whist_g[j+5][b0+2];                                       \
        QN[0] = sm->qarr[j+4];  QN[1] = sm->qarr[j+5];                       \
        IPN[0] = grcp(1.0f - QN[0]);  IPN[1] = grcp(1.0f - QN[1]);           \
    }                                                                        \
} while (0)

// process pair (j, j+1) from buffer (WA, QA, IPA) — R10 arithmetic order.
#define LP_PROC(WA, QA, IPA) do {                                            \
    const float* v1 = &sm->P[j * Nn + b0];                                   \
    const float* v2 = &sm->P[(j + 1) * Nn + b0];                             \
    const float v10 = v1[0], v11 = v1[1], v12 = v1[2];                       \
    const float v20 = v2[0], v21 = v2[1], v22 = v2[2];                       \
    float e1 = g0*v10 + g1*v11 + g2*v12;                                     \
    float e2 = g0*v20 + g1*v21 + g2*v22;                                     \
    float f  = WA[0][0]*v20 + WA[0][1]*v21 + WA[0][2]*v22;                   \
    bfly5x3(e1, e2, f);                                                      \
    const float c1  = delta * e1;                                            \
    const float q1n = QA[0] + e1 * c1;                                       \
    whist_g[j][b0+0] = WA[0][0] + c1*g0;                                     \
    whist_g[j][b0+1] = WA[0][1] + c1*g1;                                     \
    whist_g[j][b0+2] = WA[0][2] + c1*g2;                                     \
    const float t1 = e1 * IPA[0];                                            \
    const float gj0 = g0 + t1*WA[0][0];                                      \
    const float gj1 = g1 + t1*WA[0][1];                                      \
    const float gj2 = g2 + t1*WA[0][2];                                      \
    const float delta1 = delta * (1.0f - QA[0]) * grcp(1.0f - q1n);          \
    const float e2p = e2 + t1 * f;                                           \
    const float c2  = delta1 * e2p;                                          \
    const float q2n = QA[1] + e2p * c2;                                      \
    whist_g[j+1][b0+0] = WA[1][0] + c2*gj0;                                  \
    whist_g[j+1][b0+1] = WA[1][1] + c2*gj1;                                  \
    whist_g[j+1][b0+2] = WA[1][2] + c2*gj2;                                  \
    const float t2 = e2p * IPA[1];                                           \
    g0 = gj0 + t2*WA[1][0];                                                  \
    g1 = gj1 + t2*WA[1][1];                                                  \
    g2 = gj2 + t2*WA[1][2];                                                  \
    delta = delta1 * (1.0f - QA[1]) * grcp(1.0f - q2n);                      \
    if (fabsf(delta) < 1e-10f && delta != 0.0f) {                            \
        delta *= 16777216.0f;                                                \
        g0 *= 2.44140625e-4f; g1 *= 2.44140625e-4f; g2 *= 2.44140625e-4f;    \
    }                                                                        \
    if (!exited) {                                                           \
        float prob = run * q1n;                                              \
        if (!(fabsf(prob) > 1e-15f)) prob = 0.0f;                            \
        cdf += prob;                                                         \
        run *= (1.0f - q1n);                                                 \
        if (l == 0) { sm->probs[j] = prob; sm->cdfa[j] = cdf; }              \
        if (fabsf(run) < 3e-9f * cdf) { exited = 1; jend = j + 1; }          \
    }                                                                        \
    if (!exited) {                                                           \
        float prob = run * q2n;                                              \
        if (!(fabsf(prob) > 1e-15f)) prob = 0.0f;                            \
        cdf += prob;                                                         \
        run *= (1.0f - q2n);                                                 \
        if (l == 0) { sm->probs[j+1] = prob; sm->cdfa[j+1] = cdf; }          \
        if (fabsf(run) < 3e-9f * cdf) { exited = 1; jend = j + 2; }          \
    }                                                                        \
    if (l == 0) { sm->qarr[j] = q1n; sm->qarr[j+1] = q2n; }                  \
} while (0)

__device__ void light_pass(Smem* __restrict__ sm, int xmin, int F, int pos)
{
    const int l  = threadIdx.x & 31;
    const int b0 = 3 * l;
    float g0 = whist_g[pos][b0+0];
    float g1 = whist_g[pos][b0+1];
    float g2 = whist_g[pos][b0+2];
    const float qp = sm->qarr[pos];
    float delta = -(grcp(qp) + grcp(1.0f - qp));
    float run = 1.0f, cdf = 0.0f;
    int exited = 0, jend = F;
    int j = xmin;

    // triple-buffered pair data (static names -> registers)
    float wA[2][3], qA[2], ipA[2];
    float wB[2][3], qB[2], ipB[2];
    float wC[2][3], qC[2], ipC[2];

    // preload buffers A (j, j+1) and B (j+2, j+3)
    if (j + 1 < F) {
        wA[0][0] = whist_g[j][b0+0];   wA[0][1] = whist_g[j][b0+1];   wA[0][2] = whist_g[j][b0+2];
        wA[1][0] = whist_g[j+1][b0+0]; wA[1][1] = whist_g[j+1][b0+1]; wA[1][2] = whist_g[j+1][b0+2];
        qA[0] = sm->qarr[j];   qA[1] = sm->qarr[j+1];
        ipA[0] = grcp(1.0f - qA[0]);  ipA[1] = grcp(1.0f - qA[1]);
    }
    if (j + 3 < F) {
        wB[0][0] = whist_g[j+2][b0+0]; wB[0][1] = whist_g[j+2][b0+1]; wB[0][2] = whist_g[j+2][b0+2];
        wB[1][0] = whist_g[j+3][b0+0]; wB[1][1] = whist_g[j+3][b0+1]; wB[1][2] = whist_g[j+3][b0+2];
        qB[0] = sm->qarr[j+2]; qB[1] = sm->qarr[j+3];
        ipB[0] = grcp(1.0f - qB[0]);  ipB[1] = grcp(1.0f - qB[1]);
    }

    // steady state: rotate A -> B -> C -> A with depth-2 prefetch
    while (j + 1 < F) {
        LP_PREF(wC, qC, ipC);
        LP_PROC(wA, qA, ipA);
        j += 2;
        if (j + 1 >= F) break;
        LP_PREF(wA, qA, ipA);
        LP_PROC(wB, qB, ipB);
        j += 2;
        if (j + 1 >= F) break;
        LP_PREF(wB, qB, ipB);
        LP_PROC(wC, qC, ipC);
        j += 2;
    }

    // tail: single-site path (loads directly; identical to R10 tail)
    while (j < F) {
        const float w0 = whist_g[j][b0+0];
        const float w1 = whist_g[j][b0+1];
        const float w2 = whist_g[j][b0+2];
        const float qa = sm->qarr[j];
        const float* vp = &sm->P[j * Nn + b0];
        float e = g0*vp[0] + g1*vp[1] + g2*vp[2];
        e = bfly5(e);
        const float c  = delta * e;
        const float qn = qa + e * c;
        whist_g[j][b0+0] = w0 + c*g0;
        whist_g[j][b0+1] = w1 + c*g1;
        whist_g[j][b0+2] = w2 + c*g2;
        const float t = e * grcp(1.0f - qa);
        g0 += t*w0; g1 += t*w1; g2 += t*w2;
        delta = delta * (1.0f - qa) * grcp(1.0f - qn);
        if (!exited) {
            float prob = run * qn;
            if (!(fabsf(prob) > 1e-15f)) prob = 0.0f;
            cdf += prob;
            run *= (1.0f - qn);
            if (l == 0) { sm->probs[j] = prob; sm->cdfa[j] = cdf; }
            if (fabsf(run) < 3e-9f * cdf) { exited = 1; jend = j + 1; }
        }
        if (l == 0) sm->qarr[j] = qn;
        j++;
    }

    // publish correction + scan scalars
    sm->gfin[b0+0] = g0; sm->gfin[b0+1] = g1; sm->gfin[b0+2] = g2;
    if (l == 0) {
        sm->delta_s = delta;
        sm->run_s = run;  sm->cdf_s = cdf;
        sm->jend_s = exited ? jend : F;
        sm->exited_s = exited;
    }
}

// ---------------------------------------------------------------------------
// Heavy scan produce helpers (frontier sites; full matvec + reductions).
// Tiling: rt = tid>>3 (rows 3rt..3rt+2), ct = tid&7 (cols 12ct..12ct+11).
// ---------------------------------------------------------------------------
__device__ __forceinline__ void produce1(Smem* __restrict__ sm,
                                         const float C[3][12], float p1[3],
                                         int j, int buf, int rt, int ct)
{
    float v[12];
    load12(&sm->P[j * Nn + 12 * ct], v);
    p1[0] = dot12(C[0], v);
    p1[1] = dot12(C[1], v);
    p1[2] = dot12(C[2], v);
#pragma unroll
    for (int off = 1; off < 8; off <<= 1) {
        p1[0] += __shfl_xor_sync(FULLMASK, p1[0], off);
        p1[1] += __shfl_xor_sync(FULLMASK, p1[1], off);
        p1[2] += __shfl_xor_sync(FULLMASK, p1[2], off);
    }
    const float* vr = &sm->P[j * Nn + 3 * rt];
    const float qp = vr[0]*p1[0] + vr[1]*p1[1] + vr[2]*p1[2];
    if (ct == 0) {
        sm->w[buf][3*rt+0] = p1[0];
        sm->w[buf][3*rt+1] = p1[1];
        sm->w[buf][3*rt+2] = p1[2];
        sm->qpb[buf][rt] = qp;
    }
}

__device__ __forceinline__ void produce2(Smem* __restrict__ sm,
                                         const float C[3][12],
                                         float p1[3], float p2[3],
                                         int j, int buf, int rt, int ct)
{
    float v1[12], v2[12];
    load12(&sm->P[j * Nn + 12 * ct], v1);
    load12(&sm->P[(j + 1) * Nn + 12 * ct], v2);
#pragma unroll
    for (int a = 0; a < 3; a++) {
        p1[a] = dot12(C[a], v1);
        p2[a] = dot12(C[a], v2);
    }
#pragma unroll
    for (int off = 1; off < 8; off <<= 1) {
        p1[0] += __shfl_xor_sync(FULLMASK, p1[0], off);
        p1[1] += __shfl_xor_sync(FULLMASK, p1[1], off);
        p1[2] += __shfl_xor_sync(FULLMASK, p1[2], off);
        p2[0] += __shfl_xor_sync(FULLMASK, p2[0], off);
        p2[1] += __shfl_xor_sync(FULLMASK, p2[1], off);
        p2[2] += __shfl_xor_sync(FULLMASK, p2[2], off);
    }
    const float* vr1 = &sm->P[j * Nn + 3 * rt];
    const float* vr2 = &sm->P[(j + 1) * Nn + 3 * rt];
    const float q1p = vr1[0]*p1[0] + vr1[1]*p1[1] + vr1[2]*p1[2];
    const float sp  = vr2[0]*p1[0] + vr2[1]*p1[1] + vr2[2]*p1[2];
    const float q2p = vr2[0]*p2[0] + vr2[1]*p2[1] + vr2[2]*p2[2];
    if (ct == 0) {
        sm->w[buf][3*rt+0]    = p1[0];
        sm->w[buf][3*rt+1]    = p1[1];
        sm->w[buf][3*rt+2]    = p1[2];
        sm->w[buf][Nn+3*rt+0] = p2[0];
        sm->w[buf][Nn+3*rt+1] = p2[1];
        sm->w[buf][Nn+3*rt+2] = p2[2];
        sm->qpb[buf][rt]      = q1p;
        sm->qpb[buf][32 + rt] = sp;
        sm->qpb[buf][64 + rt] = q2p;
    }
}

__global__ void __launch_bounds__(TPB, 1)
sds_kernel(const float* __restrict__ eig, const float* __restrict__ u,
           float* __restrict__ out)
{
    extern __shared__ unsigned char smraw[];
    Smem* sm = reinterpret_cast<Smem*>(smraw);
    const int tid  = threadIdx.x;
    const int lane = tid & 31;
    const int warp = tid >> 5;
    const int rt   = tid >> 3;   // rows 3rt..3rt+2
    const int ct   = tid & 7;    // cols 12ct..12ct+11

    // Load P = eigfunc[:, :96] (first 96 of each 384-row).
    for (int idx = tid; idx < Dn * Nn; idx += TPB) {
        const int r = idx / Nn, c = idx - r * Nn;
        sm->P[idx] = eig[r * Dn + c];
    }

    // Persistent speculative frontier state cw: current epoch's chain with all
    // sites [0, F) conditioned empty. Starts as I.
    float cw[3][12];
#pragma unroll
    for (int a = 0; a < 3; a++)
#pragma unroll
        for (int b = 0; b < 12; b++)
            cw[a][b] = (3 * rt + a == 12 * ct + b) ? 1.0f : 0.0f;

    __syncthreads();

    int prev = -1;
    int F = 0;   // frontier: sites [0, F) have current-epoch stored (q, w)
    for (int k = 0; k < Nn; k++) {
        const int xmin = prev + 1;
        const int xmax = Dn - Nn + k + 1;   // exclusive
        const float uk = u[k];

        float run, cdf;
        int exited, jend;

        if (k > 0) {
            if (warp == 0) light_pass(sm, xmin, F, prev);
            __syncthreads();
            // materialize the correction into cw: cw += delta * g g^T
            const float dlt = sm->delta_s;
            const float gr0 = sm->gfin[3*rt+0];
            const float gr1 = sm->gfin[3*rt+1];
            const float gr2 = sm->gfin[3*rt+2];
            float gc[12];
            load12(&sm->gfin[12*ct], gc);
            const float t0 = dlt * gr0, t1 = dlt * gr1, t2 = dlt * gr2;
#pragma unroll
            for (int b = 0; b < 12; b++) {
                cw[0][b] += t0 * gc[b];
                cw[1][b] += t1 * gc[b];
                cw[2][b] += t2 * gc[b];
            }
            run = sm->run_s; cdf = sm->cdf_s;
            exited = sm->exited_s; jend = sm->jend_s;
        } else {
            run = 1.0f; cdf = 0.0f; exited = 0; jend = F;
        }

        // ---- heavy scan at the frontier ----
        if (!exited) {
            int buf = 0;
            int j = F;
            int nb = (xmax - j >= 2) ? 2 : 1;
            float p1[3], p2[3];
            if (nb == 2) produce2(sm, cw, p1, p2, j, buf, rt, ct);
            else         produce1(sm, cw, p1, j, buf, rt, ct);
            for (;;) {
                __syncthreads();
                if (nb == 2) {
                    float wc1[12], wc2[12];
                    load12(&sm->w[buf][12 * ct], wc1);
                    load12(&sm->w[buf][Nn + 12 * ct], wc2);
                    const float q1  = sum32(&sm->qpb[buf][0]);
                    const float s   = sum32(&sm->qpb[buf][32]);
                    const float q2r = sum32(&sm->qpb[buf][64]);
                    const float inv1 = grcp(1.0f - q1);
                    const float t = inv1 * s;
                    const float q2 = q2r + t * s;      // Schur-corrected
                    const float inv2 = grcp(1.0f - q2);
                    float p2c[3], wc2c[12];
#pragma unroll
                    for (int a = 0; a < 3; a++) p2c[a] = p2[a] + t * p1[a];
#pragma unroll
                    for (int b = 0; b < 12; b++) wc2c[b] = wc2[b] + t * wc1[b];

                    if (ct == 0) {
#pragma unroll
                        for (int a = 0; a < 3; a++) {
                            whist_g[j][3*rt+a]   = p1[a];
                            whist_g[j+1][3*rt+a] = p2c[a];
                        }
                    }
                    if (tid == 0) { sm->qarr[j] = q1; sm->qarr[j+1] = q2; }
                    // rank-2 update
#pragma unroll
                    for (int a = 0; a < 3; a++) {
                        const float u1 = p1[a]  * inv1;
                        const float u2 = p2c[a] * inv2;
#pragma unroll
                        for (int b = 0; b < 12; b++) {
                            cw[a][b] += u1 * wc1[b];
                            cw[a][b] += u2 * wc2c[b];
                        }
                    }
                    float prob = run * q1;
                    if (!(fabsf(prob) > 1e-15f)) prob = 0.0f;
                    cdf += prob;
                    if (tid == 0) { sm->probs[j] = prob; sm->cdfa[j] = cdf; }
                    run *= (1.0f - q1);
                    prob = run * q2;
                    if (!(fabsf(prob) > 1e-15f)) prob = 0.0f;
                    cdf += prob;
                    if (tid == 0) { sm->probs[j+1] = prob; sm->cdfa[j+1] = cdf; }
                    run *= (1.0f - q2);
                } else {
                    float wc1[12];
                    load12(&sm->w[buf][12 * ct], wc1);
                    const float q1 = sum32(&sm->qpb[buf][0]);
                    const float inv1 = grcp(1.0f - q1);
                    if (ct == 0) {
#pragma unroll
                        for (int a = 0; a < 3; a++)
                            whist_g[j][3*rt+a] = p1[a];
                    }
                    if (tid == 0) sm->qarr[j] = q1;
#pragma unroll
                    for (int a = 0; a < 3; a++) {
                        const float t = p1[a] * inv1;
#pragma unroll
                        for (int b = 0; b < 12; b++) cw[a][b] += t * wc1[b];
                    }
                    float prob = run * q1;
                    if (!(fabsf(prob) > 1e-15f)) prob = 0.0f;
                    cdf += prob;
                    if (tid == 0) { sm->probs[j] = prob; sm->cdfa[j] = cdf; }
                    run *= (1.0f - q1);
                }

                const int jn = j + nb;
                const bool stop = (fabsf(run) < 3e-9f * cdf);
                if (stop || jn >= xmax) { jend = jn; break; }
                const int nb2 = (xmax - jn >= 2) ? 2 : 1;
                if (nb2 == 2) produce2(sm, cw, p1, p2, jn, buf ^ 1, rt, ct);
                else          produce1(sm, cw, p1, jn, buf ^ 1, rt, ct);
                buf ^= 1; j = jn; nb = nb2;
            }
            F = jend;   // frontier advanced; every stored site is cur-epoch
        }
        __syncthreads();   // probs/cdfa/qarr/whist visible

        // ---- position selection: pos = xmin + #{ cdfa[j] < u*total } ----
        const float thr = uk * cdf;
        const int len = jend - xmin;            // <= 289 (2 elems/thread)
        int cnt_t = 0;
        if (tid < len       && sm->cdfa[xmin + tid]       < thr) cnt_t++;
        if (tid + TPB < len && sm->cdfa[xmin + tid + TPB] < thr) cnt_t++;
        const int wsum = __reduce_add_sync(FULLMASK, cnt_t);
        if (lane == 0) sm->cnt[warp] = wsum;
        __syncthreads();
        int tot = 0;
#pragma unroll
        for (int i = 0; i < 8; i++) tot += sm->cnt[i];
        int pos = xmin + tot;
        if (pos > jend - 1) pos = jend - 1;

        if (tid == 0) {
            out[k]      = (float)pos;       // positions, then cond_probs
            out[Nn + k] = sm->probs[pos];
        }
        prev = pos;
        __syncthreads();   // qarr/whist stable before next light pass
    }
}

extern "C" void kernel_launch(void* const* d_in, const int* in_sizes, int n_in,
                              void* d_out, int out_size)
{
    (void)in_sizes; (void)n_in; (void)out_size;
    const float* eig = (const float*)d_in[0];   // eigfunc (384,384) f32
    const float* uu  = (const float*)d_in[1];   // u (96,) f32
    float* out = (float*)d_out;                 // [positions(96); cond_probs(96)]

    cudaFuncSetAttribute(sds_kernel,
                         cudaFuncAttributeMaxDynamicSharedMemorySize,
                         (int)sizeof(Smem));
    sds_kernel<<<1, TPB, sizeof(Smem)>>>(eig, uu, out);
}

// round 13
// speedup vs baseline: 1.8480x; 1.8480x over previous
#include <cuda_runtime.h>
#include <math.h>

#define Dn 384
#define Nn 96
#define TPB 256
#define FULLMASK 0xffffffffu

// Per-site chain vectors w_j = C_{j-1} v_j (current epoch), L2-resident.
__device__ float whist_g[Dn][Nn];

// Dynamic shared memory (~152 KB).
struct Smem {
    float P[Dn * Nn];                 // eigfunc[:, :96] row-major [site][comp]
    float qarr[Dn];                   // per-site pivot complement q (cur epoch)
    float probs[Dn];                  // window probs (current step)
    float cdfa[Dn];                   // running cdf (current step)
    __align__(16) float w[2][2 * Nn]; // heavy: [buf][ w1(96) | w2(96) ]
    __align__(16) float qpb[2][96];   // heavy: [buf][ q1p | sp | q2p ] x32
    __align__(16) float gfin[Nn];     // light: final correction vector
    float delta_s;
    float runF_s, cdfF_s;             // light: run/cdf carried to F
    float arl_s, cdfl_s, cdfs_s;      // loose/strict exit records
    int   jl_s, js_s, exl_s, exs_s;
    int   cnt[8];
};

__device__ __forceinline__ float grcp(float x) {
    return (fabsf(x) > 1e-30f) ? __frcp_rn(x) : 0.0f;
}

__device__ __forceinline__ void load12(const float* src, float d[12]) {
    const float4* s4 = reinterpret_cast<const float4*>(src);
    float4 a = s4[0], b = s4[1], c = s4[2];
    d[0]=a.x; d[1]=a.y; d[2]=a.z; d[3]=a.w;
    d[4]=b.x; d[5]=b.y; d[6]=b.z; d[7]=b.w;
    d[8]=c.x; d[9]=c.y; d[10]=c.z; d[11]=c.w;
}

// Deterministic fixed-order sum of 32 floats (16B-aligned smem).
__device__ __forceinline__ float sum32(const float* q) {
    const float4* q4 = reinterpret_cast<const float4*>(q);
    float t[8];
#pragma unroll
    for (int i = 0; i < 8; i++) {
        float4 v = q4[i];
        t[i] = (v.x + v.y) + (v.z + v.w);
    }
    return ((t[0]+t[1]) + (t[2]+t[3])) + ((t[4]+t[5]) + (t[6]+t[7]));
}

// Balanced 12-term dot (4 accumulators), fixed order.
__device__ __forceinline__ float dot12(const float* c, const float v[12]) {
    float a = c[0]*v[0]; a = fmaf(c[4], v[4], a); a = fmaf(c[8],  v[8],  a);
    float b = c[1]*v[1]; b = fmaf(c[5], v[5], b); b = fmaf(c[9],  v[9],  b);
    float d = c[2]*v[2]; d = fmaf(c[6], v[6], d); d = fmaf(c[10], v[10], d);
    float e = c[3]*v[3]; e = fmaf(c[7], v[7], e); e = fmaf(c[11], v[11], e);
    return (a + b) + (d + e);
}

__device__ __forceinline__ void bfly5x3(float& a, float& b, float& c) {
#pragma unroll
    for (int off = 16; off; off >>= 1) {
        a += __shfl_xor_sync(FULLMASK, a, off);
        b += __shfl_xor_sync(FULLMASK, b, off);
        c += __shfl_xor_sync(FULLMASK, c, off);
    }
}
__device__ __forceinline__ float bfly5(float a) {
#pragma unroll
    for (int off = 16; off; off >>= 1)
        a += __shfl_xor_sync(FULLMASK, a, off);
    return a;
}

// ---------------------------------------------------------------------------
// Light pass (warp 0 only; lane l owns components 3l..3l+2).
// R10 arithmetic, verbatim. Refreshes (q, w) for ALL of [xmin, F); writes
// probs/cdfa for all sites; tracks BOTH the loose and strict exit points.
// Loose exit: (u*(cdf+|run|) < cdf*(1-1e-4)) && (|run| < 3e-4*cdf)
// Strict exit: |run| < 3e-9*cdf
// ---------------------------------------------------------------------------
__device__ void light_pass(Smem* __restrict__ sm, int xmin, int F, int pos,
                           float uk)
{
    const int l  = threadIdx.x & 31;
    const int b0 = 3 * l;
    float g0 = whist_g[pos][b0+0];
    float g1 = whist_g[pos][b0+1];
    float g2 = whist_g[pos][b0+2];
    const float qp = sm->qarr[pos];
    float delta = -(grcp(qp) + grcp(1.0f - qp));
    float run = 1.0f, cdf = 0.0f;
    int exl = 0, jl = F, exs = 0, js = F;
    float arl = 0.0f, cdfl = 0.0f, cdfs = 0.0f;
    int j = xmin;

    float wa0=0,wa1=0,wa2=0, wb0=0,wb1=0,wb2=0, qa=0, qb=0;
    if (j < F) {
        wa0 = whist_g[j][b0+0]; wa1 = whist_g[j][b0+1]; wa2 = whist_g[j][b0+2];
        qa  = sm->qarr[j];
    }
    if (j + 1 < F) {
        wb0 = whist_g[j+1][b0+0]; wb1 = whist_g[j+1][b0+1]; wb2 = whist_g[j+1][b0+2];
        qb  = sm->qarr[j+1];
    }

    while (j + 1 < F) {
        // prefetch next pair (depth-1, as in R10)
        float na0=0,na1=0,na2=0, nb0=0,nb1=0,nb2=0, qna=0, qnb=0;
        if (j + 2 < F) {
            na0 = whist_g[j+2][b0+0]; na1 = whist_g[j+2][b0+1]; na2 = whist_g[j+2][b0+2];
            qna = sm->qarr[j+2];
        }
        if (j + 3 < F) {
            nb0 = whist_g[j+3][b0+0]; nb1 = whist_g[j+3][b0+1]; nb2 = whist_g[j+3][b0+2];
            qnb = sm->qarr[j+3];
        }
        const float* v1 = &sm->P[j * Nn + b0];
        const float* v2 = &sm->P[(j + 1) * Nn + b0];
        const float v10 = v1[0], v11 = v1[1], v12 = v1[2];
        const float v20 = v2[0], v21 = v2[1], v22 = v2[2];

        float e1 = g0*v10 + g1*v11 + g2*v12;    // g . v_j
        float e2 = g0*v20 + g1*v21 + g2*v22;    // g . v_{j+1}
        float f  = wa0*v20 + wa1*v21 + wa2*v22; // w_j . v_{j+1}
        bfly5x3(e1, e2, f);

        // ---- site j ----
        const float c1  = delta * e1;
        const float q1n = qa + e1 * c1;
        whist_g[j][b0+0] = wa0 + c1*g0;
        whist_g[j][b0+1] = wa1 + c1*g1;
        whist_g[j][b0+2] = wa2 + c1*g2;
        const float ia = grcp(1.0f - qa);
        const float t1 = e1 * ia;
        const float gj0 = g0 + t1*wa0;
        const float gj1 = g1 + t1*wa1;
        const float gj2 = g2 + t1*wa2;
        const float delta1 = delta * (1.0f - qa) * grcp(1.0f - q1n);

        // ---- site j+1 ----
        const float e2p = e2 + t1 * f;           // g_j . v_{j+1}
        const float c2  = delta1 * e2p;
        const float q2n = qb + e2p * c2;
        whist_g[j+1][b0+0] = wb0 + c2*gj0;
        whist_g[j+1][b0+1] = wb1 + c2*gj1;
        whist_g[j+1][b0+2] = wb2 + c2*gj2;
        const float ib = grcp(1.0f - qb);
        const float t2 = e2p * ib;
        g0 = gj0 + t2*wb0;
        g1 = gj1 + t2*wb1;
        g2 = gj2 + t2*wb2;
        delta = delta1 * (1.0f - qb) * grcp(1.0f - q2n);

        // exact renormalization: delta*2^24, g*2^-12 (fp-exact)
        if (fabsf(delta) < 1e-10f && delta != 0.0f) {
            delta *= 16777216.0f;
            g0 *= 2.44140625e-4f; g1 *= 2.44140625e-4f; g2 *= 2.44140625e-4f;
        }

        // bookkeeping (replicated scalars; lane 0 writes) — always to F
        {
            float prob = run * q1n;
            if (!(fabsf(prob) > 1e-15f)) prob = 0.0f;
            cdf += prob;
            run *= (1.0f - q1n);
            if (l == 0) { sm->probs[j] = prob; sm->cdfa[j] = cdf; }
            const float ar = fabsf(run);
            if (!exs && ar < 3e-9f * cdf) { exs = 1; js = j + 1; cdfs = cdf; }
            if (!exl && (uk * (cdf + ar) < cdf * (1.0f - 1e-4f)) &&
                (ar < 3e-4f * cdf)) { exl = 1; jl = j + 1; arl = ar; cdfl = cdf; }
        }
        {
            float prob = run * q2n;
            if (!(fabsf(prob) > 1e-15f)) prob = 0.0f;
            cdf += prob;
            run *= (1.0f - q2n);
            if (l == 0) { sm->probs[j+1] = prob; sm->cdfa[j+1] = cdf; }
            const float ar = fabsf(run);
            if (!exs && ar < 3e-9f * cdf) { exs = 1; js = j + 2; cdfs = cdf; }
            if (!exl && (uk * (cdf + ar) < cdf * (1.0f - 1e-4f)) &&
                (ar < 3e-4f * cdf)) { exl = 1; jl = j + 2; arl = ar; cdfl = cdf; }
        }
        if (l == 0) { sm->qarr[j] = q1n; sm->qarr[j+1] = q2n; }

        wa0=na0; wa1=na1; wa2=na2; qa=qna;
        wb0=nb0; wb1=nb1; wb2=nb2; qb=qnb;
        j += 2;
    }

    if (j < F) {   // odd tail, single site
        const float* vp = &sm->P[j * Nn + b0];
        float e = g0*vp[0] + g1*vp[1] + g2*vp[2];
        e = bfly5(e);
        const float c  = delta * e;
        const float qn = qa + e * c;
        whist_g[j][b0+0] = wa0 + c*g0;
        whist_g[j][b0+1] = wa1 + c*g1;
        whist_g[j][b0+2] = wa2 + c*g2;
        const float t = e * grcp(1.0f - qa);
        g0 += t*wa0; g1 += t*wa1; g2 += t*wa2;
        delta = delta * (1.0f - qa) * grcp(1.0f - qn);
        float prob = run * qn;
        if (!(fabsf(prob) > 1e-15f)) prob = 0.0f;
        cdf += prob;
        run *= (1.0f - qn);
        if (l == 0) { sm->probs[j] = prob; sm->cdfa[j] = cdf; }
        const float ar = fabsf(run);
        if (!exs && ar < 3e-9f * cdf) { exs = 1; js = j + 1; cdfs = cdf; }
        if (!exl && (uk * (cdf + ar) < cdf * (1.0f - 1e-4f)) &&
            (ar < 3e-4f * cdf)) { exl = 1; jl = j + 1; arl = ar; cdfl = cdf; }
        if (l == 0) sm->qarr[j] = qn;
        j++;
    }

    // publish correction + scan scalars
    sm->gfin[b0+0] = g0; sm->gfin[b0+1] = g1; sm->gfin[b0+2] = g2;
    if (l == 0) {
        sm->delta_s = delta;
        sm->runF_s = run;  sm->cdfF_s = cdf;
        sm->exl_s = exl; sm->jl_s = jl; sm->arl_s = arl; sm->cdfl_s = cdfl;
        sm->exs_s = exs; sm->js_s = js; sm->cdfs_s = cdfs;
    }
}

// ---------------------------------------------------------------------------
// Heavy scan produce helpers (frontier sites; full matvec + reductions).
// Tiling: rt = tid>>3 (rows 3rt..3rt+2), ct = tid&7 (cols 12ct..12ct+11).
// ---------------------------------------------------------------------------
__device__ __forceinline__ void produce1(Smem* __restrict__ sm,
                                         const float C[3][12], float p1[3],
                                         int j, int buf, int rt, int ct)
{
    float v[12];
    load12(&sm->P[j * Nn + 12 * ct], v);
    p1[0] = dot12(C[0], v);
    p1[1] = dot12(C[1], v);
    p1[2] = dot12(C[2], v);
#pragma unroll
    for (int off = 1; off < 8; off <<= 1) {
        p1[0] += __shfl_xor_sync(FULLMASK, p1[0], off);
        p1[1] += __shfl_xor_sync(FULLMASK, p1[1], off);
        p1[2] += __shfl_xor_sync(FULLMASK, p1[2], off);
    }
    const float* vr = &sm->P[j * Nn + 3 * rt];
    const float qp = vr[0]*p1[0] + vr[1]*p1[1] + vr[2]*p1[2];
    if (ct == 0) {
        sm->w[buf][3*rt+0] = p1[0];
        sm->w[buf][3*rt+1] = p1[1];
        sm->w[buf][3*rt+2] = p1[2];
        sm->qpb[buf][rt] = qp;
    }
}

__device__ __forceinline__ void produce2(Smem* __restrict__ sm,
                                         const float C[3][12],
                                         float p1[3], float p2[3],
                                         int j, int buf, int rt, int ct)
{
    float v1[12], v2[12];
    load12(&sm->P[j * Nn + 12 * ct], v1);
    load12(&sm->P[(j + 1) * Nn + 12 * ct], v2);
#pragma unroll
    for (int a = 0; a < 3; a++) {
        p1[a] = dot12(C[a], v1);
        p2[a] = dot12(C[a], v2);
    }
#pragma unroll
    for (int off = 1; off < 8; off <<= 1) {
        p1[0] += __shfl_xor_sync(FULLMASK, p1[0], off);
        p1[1] += __shfl_xor_sync(FULLMASK, p1[1], off);
        p1[2] += __shfl_xor_sync(FULLMASK, p1[2], off);
        p2[0] += __shfl_xor_sync(FULLMASK, p2[0], off);
        p2[1] += __shfl_xor_sync(FULLMASK, p2[1], off);
        p2[2] += __shfl_xor_sync(FULLMASK, p2[2], off);
    }
    const float* vr1 = &sm->P[j * Nn + 3 * rt];
    const float* vr2 = &sm->P[(j + 1) * Nn + 3 * rt];
    const float q1p = vr1[0]*p1[0] + vr1[1]*p1[1] + vr1[2]*p1[2];
    const float sp  = vr2[0]*p1[0] + vr2[1]*p1[1] + vr2[2]*p1[2];
    const float q2p = vr2[0]*p2[0] + vr2[1]*p2[1] + vr2[2]*p2[2];
    if (ct == 0) {
        sm->w[buf][3*rt+0]    = p1[0];
        sm->w[buf][3*rt+1]    = p1[1];
        sm->w[buf][3*rt+2]    = p1[2];
        sm->w[buf][Nn+3*rt+0] = p2[0];
        sm->w[buf][Nn+3*rt+1] = p2[1];
        sm->w[buf][Nn+3*rt+2] = p2[2];
        sm->qpb[buf][rt]      = q1p;
        sm->qpb[buf][32 + rt] = sp;
        sm->qpb[buf][64 + rt] = q2p;
    }
}

// Heavy frontier scan from jstart with dual stop. Updates run/cdf in place.
// All control scalars replicated across threads (uniform barriers).
__device__ __forceinline__ void heavy_scan(Smem* __restrict__ sm,
    float (&cw)[3][12], int jstart, int xmax, float& run, float& cdf,
    int strict, float uk, int rt, int ct, int tid,
    int& jend_out, int& by_loose_out)
{
    if (jstart >= xmax) { jend_out = jstart; by_loose_out = 0; return; }
    int buf = 0;
    int j = jstart;
    int nb = (xmax - j >= 2) ? 2 : 1;
    float p1[3], p2[3];
    if (nb == 2) produce2(sm, cw, p1, p2, j, buf, rt, ct);
    else         produce1(sm, cw, p1, j, buf, rt, ct);
    for (;;) {
        __syncthreads();
        if (nb == 2) {
            float wc1[12], wc2[12];
            load12(&sm->w[buf][12 * ct], wc1);
            load12(&sm->w[buf][Nn + 12 * ct], wc2);
            const float q1  = sum32(&sm->qpb[buf][0]);
            const float s   = sum32(&sm->qpb[buf][32]);
            const float q2r = sum32(&sm->qpb[buf][64]);
            const float inv1 = grcp(1.0f - q1);
            const float t = inv1 * s;
            const float q2 = q2r + t * s;      // Schur-corrected
            const float inv2 = grcp(1.0f - q2);
            float p2c[3], wc2c[12];
#pragma unroll
            for (int a = 0; a < 3; a++) p2c[a] = p2[a] + t * p1[a];
#pragma unroll
            for (int b = 0; b < 12; b++) wc2c[b] = wc2[b] + t * wc1[b];

            if (ct == 0) {
#pragma unroll
                for (int a = 0; a < 3; a++) {
                    whist_g[j][3*rt+a]   = p1[a];
                    whist_g[j+1][3*rt+a] = p2c[a];
                }
            }
            if (tid == 0) { sm->qarr[j] = q1; sm->qarr[j+1] = q2; }
#pragma unroll
            for (int a = 0; a < 3; a++) {
                const float u1 = p1[a]  * inv1;
                const float u2 = p2c[a] * inv2;
#pragma unroll
                for (int b = 0; b < 12; b++) {
                    cw[a][b] += u1 * wc1[b];
                    cw[a][b] += u2 * wc2c[b];
                }
            }
            float prob = run * q1;
            if (!(fabsf(prob) > 1e-15f)) prob = 0.0f;
            cdf += prob;
            if (tid == 0) { sm->probs[j] = prob; sm->cdfa[j] = cdf; }
            run *= (1.0f - q1);
            prob = run * q2;
            if (!(fabsf(prob) > 1e-15f)) prob = 0.0f;
            cdf += prob;
            if (tid == 0) { sm->probs[j+1] = prob; sm->cdfa[j+1] = cdf; }
            run *= (1.0f - q2);
        } else {
            float wc1[12];
            load12(&sm->w[buf][12 * ct], wc1);
            const float q1 = sum32(&sm->qpb[buf][0]);
            const float inv1 = grcp(1.0f - q1);
            if (ct == 0) {
#pragma unroll
                for (int a = 0; a < 3; a++)
                    whist_g[j][3*rt+a] = p1[a];
            }
            if (tid == 0) sm->qarr[j] = q1;
#pragma unroll
            for (int a = 0; a < 3; a++) {
                const float t = p1[a] * inv1;
#pragma unroll
                for (int b = 0; b < 12; b++) cw[a][b] += t * wc1[b];
            }
            float prob = run * q1;
            if (!(fabsf(prob) > 1e-15f)) prob = 0.0f;
            cdf += prob;
            if (tid == 0) { sm->probs[j] = prob; sm->cdfa[j] = cdf; }
            run *= (1.0f - q1);
        }

        const int jn = j + nb;
        const float ar = fabsf(run);
        const bool stop_s = (ar < 3e-9f * cdf);
        bool stop_l = false;
        if (!strict)
            stop_l = ((uk * (cdf + ar) < cdf * (1.0f - 1e-4f)) &&
                      (ar < 3e-4f * cdf));
        if (stop_s || stop_l || jn >= xmax) {
            jend_out = jn;
            by_loose_out = (stop_l && !stop_s && jn < xmax) ? 1 : 0;
            break;
        }
        const int nb2 = (xmax - jn >= 2) ? 2 : 1;
        if (nb2 == 2) produce2(sm, cw, p1, p2, jn, buf ^ 1, rt, ct);
        else          produce1(sm, cw, p1, jn, buf ^ 1, rt, ct);
        buf ^= 1; j = jn; nb = nb2;
    }
}

__global__ void __launch_bounds__(TPB, 1)
sds_kernel(const float* __restrict__ eig, const float* __restrict__ u,
           float* __restrict__ out)
{
    extern __shared__ unsigned char smraw[];
    Smem* sm = reinterpret_cast<Smem*>(smraw);
    const int tid  = threadIdx.x;
    const int lane = tid & 31;
    const int warp = tid >> 5;
    const int rt   = tid >> 3;   // rows 3rt..3rt+2
    const int ct   = tid & 7;    // cols 12ct..12ct+11

    // Load P = eigfunc[:, :96] (first 96 of each 384-row).
    for (int idx = tid; idx < Dn * Nn; idx += TPB) {
        const int r = idx / Nn, c = idx - r * Nn;
        sm->P[idx] = eig[r * Dn + c];
    }

    // Persistent speculative frontier state cw (all of [0,F) empty). Starts I.
    float cw[3][12];
#pragma unroll
    for (int a = 0; a < 3; a++)
#pragma unroll
        for (int b = 0; b < 12; b++)
            cw[a][b] = (3 * rt + a == 12 * ct + b) ? 1.0f : 0.0f;

    __syncthreads();

    int prev = -1;
    int F = 0;   // frontier: sites [0, F) have current-epoch stored (q, w)
    for (int k = 0; k < Nn; k++) {
        const int xmin = prev + 1;
        const int xmax = Dn - Nn + k + 1;   // exclusive
        const float uk = u[k];

        float runF, cdfF, arl = 0.0f, cdfl = 0.0f, cdfs = 0.0f;
        int exl, exs, jl = F, js = F;

        if (k > 0) {
            if (warp == 0) light_pass(sm, xmin, F, prev, uk);
            __syncthreads();
            // materialize the correction into cw: cw += delta * g g^T
            const float dlt = sm->delta_s;
            const float gr0 = sm->gfin[3*rt+0];
            const float gr1 = sm->gfin[3*rt+1];
            const float gr2 = sm->gfin[3*rt+2];
            float gc[12];
            load12(&sm->gfin[12*ct], gc);
            const float t0 = dlt * gr0, t1 = dlt * gr1, t2 = dlt * gr2;
#pragma unroll
            for (int b = 0; b < 12; b++) {
                cw[0][b] += t0 * gc[b];
                cw[1][b] += t1 * gc[b];
                cw[2][b] += t2 * gc[b];
            }
            runF = sm->runF_s; cdfF = sm->cdfF_s;
            exl = sm->exl_s; jl = sm->jl_s; arl = sm->arl_s; cdfl = sm->cdfl_s;
            exs = sm->exs_s; js = sm->js_s; cdfs = sm->cdfs_s;
        } else {
            runF = 1.0f; cdfF = 0.0f; exl = 0; exs = 0;
        }

        // ---- determine selection window (loose-first, verified) ----
        int jend; float selcdf, selar = 0.0f; int loose;
        int need_heavy, strictm = 0;
        float hrun = runF, hcdf = cdfF;
        const int from_light_loose = exl;
        if (exl)      { jend = jl; selcdf = cdfl; selar = arl; loose = 1; need_heavy = 0; }
        else if (exs) { jend = js; selcdf = cdfs; loose = 0; need_heavy = 0; }
        else          { need_heavy = 1; loose = 0; jend = F; selcdf = cdfF; }

        int pos = -1;
        for (int attempt = 0; attempt < 2; attempt++) {
            if (need_heavy) {
                int je, bl;
                heavy_scan(sm, cw, F, xmax, hrun, hcdf, strictm, uk,
                           rt, ct, tid, je, bl);
                jend = je; F = je;
                selcdf = hcdf; selar = fabsf(hrun); loose = bl;
                need_heavy = 0;
            }
            __syncthreads();   // probs/cdfa visible; orders cnt reuse

            const int len = jend - xmin;        // <= 289 (2 elems/thread)
            if (loose) {
                const float thr_mid = uk * selcdf;
                const float thr_lo  = thr_mid * (1.0f - 3e-6f);
                const float thr_hi  = uk * (selcdf + selar) * (1.0f + 3e-6f);
                int packed = 0;
                if (tid < len) {
                    const float cv = sm->cdfa[xmin + tid];
                    packed += (cv < thr_lo ? 1 : 0)
                            + ((cv < thr_mid ? 1 : 0) << 10)
                            + ((cv < thr_hi ? 1 : 0) << 20);
                }
                if (tid + TPB < len) {
                    const float cv = sm->cdfa[xmin + tid + TPB];
                    packed += (cv < thr_lo ? 1 : 0)
                            + ((cv < thr_mid ? 1 : 0) << 10)
                            + ((cv < thr_hi ? 1 : 0) << 20);
                }
                const int wsum = __reduce_add_sync(FULLMASK, packed);
                if (lane == 0) sm->cnt[warp] = wsum;
                __syncthreads();
                int tot = 0;
#pragma unroll
                for (int i = 0; i < 8; i++) tot += sm->cnt[i];
                const int c_lo  = tot & 1023;
                const int c_hi  = (tot >> 20) & 1023;
                int p_lo = xmin + c_lo;  if (p_lo > jend - 1) p_lo = jend - 1;
                int p_hi = xmin + c_hi;  if (p_hi > jend - 1) p_hi = jend - 1;
                if (p_lo == p_hi) { pos = p_lo; break; }
                // ambiguous: fall back to strict
                if (from_light_loose && exs) {
                    jend = js; selcdf = cdfs; loose = 0; need_heavy = 0;
                } else {
                    // resume heavy with strict stop (hrun/hcdf hold state at F)
                    need_heavy = 1; strictm = 1; loose = 0;
                }
            } else {
                const float thr = uk * selcdf;
                int cnt_t = 0;
                if (tid < len       && sm->cdfa[xmin + tid]       < thr) cnt_t++;
                if (tid + TPB < len && sm->cdfa[xmin + tid + TPB] < thr) cnt_t++;
                const int wsum = __reduce_add_sync(FULLMASK, cnt_t);
                if (lane == 0) sm->cnt[warp] = wsum;
                __syncthreads();
                int tot = 0;
#pragma unroll
                for (int i = 0; i < 8; i++) tot += sm->cnt[i];
                pos = xmin + tot;
                if (pos > jend - 1) pos = jend - 1;
                break;
            }
        }

        if (tid == 0) {
            out[k]      = (float)pos;       // positions, then cond_probs
            out[Nn + k] = sm->probs[pos];
        }
        prev = pos;
        __syncthreads();   // qarr/whist/cnt stable before next step
    }
}

extern "C" void kernel_launch(void* const* d_in, const int* in_sizes, int n_in,
                              void* d_out, int out_size)
{
    (void)in_sizes; (void)n_in; (void)out_size;
    const float* eig = (const float*)d_in[0];   // eigfunc (384,384) f32
    const float* uu  = (const float*)d_in[1];   // u (96,) f32
    float* out = (float*)d_out;                 // [positions(96); cond_probs(96)]

    cudaFuncSetAttribute(sds_kernel,
                         cudaFuncAttributeMaxDynamicSharedMemorySize,
                         (int)sizeof(Smem));
    sds_kernel<<<1, TPB, sizeof(Smem)>>>(eig, uu, out);
}